// round 5
// baseline (speedup 1.0000x reference)
#include <cuda_runtime.h>
#include <cuda_bf16.h>
#include <cstdint>
#include <cstddef>

// ============================================================================
// Problem constants: B=4096, D=512, 2B=8192 rows, temperature 0.1
// ============================================================================
#define B_ROWS 4096
#define DIM    512
#define NROWS  8192

// Scratch (device globals — no allocation allowed)
__device__ __align__(128) __nv_bfloat16 g_F[NROWS * DIM];   // normalized features, bf16
__device__ float g_psum[2 * NROWS];  // per-row partial exp-sums (per col-half)
__device__ float g_pos[NROWS];       // positive-pair dot product (unscaled)
__device__ float g_bsum[8];          // block partial sums of NLL

// ============================================================================
// Arch-neutral PTX helpers (no 'a'-suffix features: ptxas target is sm_103)
// ============================================================================
static __device__ __forceinline__ uint32_t smem_u32(const void* p) {
    uint32_t a;
    asm("{ .reg .u64 t; cvta.to.shared.u64 t, %1; cvt.u32.u64 %0, t; }" : "=r"(a) : "l"(p));
    return a;
}
static __device__ __forceinline__ void ldsm4(uint32_t* r, uint32_t addr) {
    asm volatile("ldmatrix.sync.aligned.m8n8.x4.shared.b16 {%0,%1,%2,%3}, [%4];"
        : "=r"(r[0]), "=r"(r[1]), "=r"(r[2]), "=r"(r[3]) : "r"(addr));
}
static __device__ __forceinline__ void mma16816(float* c, const uint32_t* a,
                                                uint32_t b0, uint32_t b1) {
    asm volatile(
        "mma.sync.aligned.m16n8k16.row.col.f32.bf16.bf16.f32 "
        "{%0,%1,%2,%3}, {%4,%5,%6,%7}, {%8,%9}, {%0,%1,%2,%3};"
        : "+f"(c[0]), "+f"(c[1]), "+f"(c[2]), "+f"(c[3])
        : "r"(a[0]), "r"(a[1]), "r"(a[2]), "r"(a[3]), "r"(b0), "r"(b1));
}
static __device__ __forceinline__ void cp16(uint32_t dst, const void* src) {
    asm volatile("cp.async.cg.shared.global [%0], [%1], 16;" :: "r"(dst), "l"(src));
}
#define CP_COMMIT() asm volatile("cp.async.commit_group;" ::: "memory")
#define CP_WAIT1()  asm volatile("cp.async.wait_group 1;" ::: "memory")
static __device__ __forceinline__ float ex2f(float x) {
    float y; asm("ex2.approx.ftz.f32 %0, %1;" : "=f"(y) : "f"(x)); return y;
}

// ============================================================================
// SMEM layout (GEMM kernel). 16B row padding => ldmatrix bank-conflict-free
//   A: 128 rows x (512 bf16 = 1024B + 16B pad) = 133,120 B   (persistent)
//   B: 2 stages x (256 rows x (64 bf16 = 128B + 16B pad))    = 73,728 B
// ============================================================================
static constexpr int A_STRIDE = 1040;                 // bytes per A row
static constexpr int B_STRIDE = 144;                  // bytes per B row
static constexpr int SMA      = 0;
static constexpr int SMB      = 128 * A_STRIDE;       // 133120
static constexpr int BSTG     = 256 * B_STRIDE;       // 36864
static constexpr int SMEM_BYTES = SMB + 2 * BSTG;     // 206848

// ============================================================================
// Kernel 1: fp32 L2-normalize rows of features1|features2 -> g_F (bf16)
// ============================================================================
__global__ void __launch_bounds__(128) normalize_kernel(
    const float* __restrict__ f1, const float* __restrict__ f2)
{
    const int row = blockIdx.x;                 // 0..8191
    const int t = threadIdx.x;                  // 0..127 (4 floats each)
    const float* src = (row < B_ROWS) ? (f1 + (size_t)row * DIM)
                                      : (f2 + (size_t)(row - B_ROWS) * DIM);
    float4 v = ((const float4*)src)[t];
    float ss = v.x * v.x + v.y * v.y + v.z * v.z + v.w * v.w;
    #pragma unroll
    for (int o = 16; o > 0; o >>= 1) ss += __shfl_xor_sync(0xffffffffu, ss, o);
    __shared__ float ws[4];
    if ((t & 31) == 0) ws[t >> 5] = ss;
    __syncthreads();
    ss = ws[0] + ws[1] + ws[2] + ws[3];
    const float scale = 1.0f / fmaxf(sqrtf(ss), 1e-12f);
    __nv_bfloat162* dst = (__nv_bfloat162*)(g_F + (size_t)row * DIM);
    dst[t * 2 + 0] = __floats2bfloat162_rn(v.x * scale, v.y * scale);
    dst[t * 2 + 1] = __floats2bfloat162_rn(v.z * scale, v.w * scale);
}

// ============================================================================
// Kernel 2: fused streaming-softmax GEMM (HMMA mma.sync path).
// grid = 128: blockIdx = (row_tile<<1) | col_half.
// CTA: rows [rb*128, +128), cols [half*4096, +4096).
// 256 threads = 8 warps in a 2(row) x 4(col) grid; warp tile 64x64.
// Column stream: 16 chunks of 256 cols; K in 8 stages of 64 (cp.async 2-buf).
// ============================================================================
__global__ void __launch_bounds__(256, 1) infonce_gemm_kernel()
{
    extern __shared__ __align__(1024) char smem[];
    const uint32_t sb = smem_u32(smem);
    const int tid  = threadIdx.x;
    const int lane = tid & 31;
    const int wid  = tid >> 5;
    const int wm   = wid >> 2;                 // 0..1 : 64-row band
    const int wn   = wid & 3;                  // 0..3 : 64-col band
    const int rb   = blockIdx.x >> 1;
    const int half = blockIdx.x & 1;
    const int row0 = rb << 7;
    const int col0 = half << 12;

    // ---- load A (128 rows x 512 bf16) into padded SMEM ----
    {
        const uint4* src = (const uint4*)(g_F + (size_t)row0 * DIM);
        #pragma unroll
        for (int i = 0; i < 32; i++) {
            int idx = tid + (i << 8);          // 0..8191 16B chunks
            int r = idx >> 6, c = idx & 63;
            *(uint4*)(smem + SMA + r * A_STRIDE + c * 16) = src[idx];
        }
    }

    // ---- per-thread ldmatrix base offsets (constant across loop) ----
    // A fragment (m16k16), m-tile mt: lanes 0-7 rows 0-7, 8-15 rows 8-15,
    // 16-23 rows 0-7 k+8, 24-31 rows 8-15 k+8.
    uint32_t abase[4];
    {
        int r_l = wm * 64 + (lane & 7) + ((lane >> 3) & 1) * 8;
        int ka  = (lane >> 4) * 8;
        #pragma unroll
        for (int mt = 0; mt < 4; mt++)
            abase[mt] = sb + SMA + (uint32_t)((r_l + mt * 16) * A_STRIDE + ka * 2);
    }
    // B fragment pair (two n8 tiles, k16), pair p: lanes 0-7 n0-7 k0,
    // 8-15 n0-7 k8, 16-23 n8-15 k0, 24-31 n8-15 k8.
    uint32_t bbase[4];
    {
        int n_l = wn * 64 + (lane & 7) + (lane >> 4) * 8;
        int kb  = ((lane >> 3) & 1) * 8;
        #pragma unroll
        for (int p = 0; p < 4; p++)
            bbase[p] = sb + SMB + (uint32_t)((n_l + p * 16) * B_STRIDE + kb * 2);
    }

    float c[4][8][4];                          // 128 accumulators
    #pragma unroll
    for (int mt = 0; mt < 4; mt++)
        #pragma unroll
        for (int nt = 0; nt < 8; nt++)
            #pragma unroll
            for (int q = 0; q < 4; q++) c[mt][nt][q] = 0.0f;
    float rsum[8];
    #pragma unroll
    for (int i = 0; i < 8; i++) rsum[i] = 0.0f;

    // ---- B stage loader: stage s covers cols [col0+(s>>3)*256, +256),
    //      K [ (s&7)*64, +64 ). 2048 x 16B cp.async, 8 per thread. ----
    auto load_stage = [&](int s) {
        const int blk = s >> 3, kc = s & 7;
        const uint32_t bb = sb + SMB + (uint32_t)((s & 1) * BSTG);
        const __nv_bfloat16* base = g_F + (size_t)(col0 + blk * 256) * DIM + kc * 64;
        #pragma unroll
        for (int i = 0; i < 8; i++) {
            int idx = tid + (i << 8);          // 0..2047
            int n = idx >> 3, ck = idx & 7;
            cp16(bb + (uint32_t)(n * B_STRIDE + ck * 16),
                 base + (size_t)n * DIM + ck * 8);
        }
    };

    const float LOG2E10 = 14.426950408889634f;  // 10 / ln 2
    const int r_lo0 = row0 + wm * 64 + (lane >> 2);

    __syncthreads();                            // A visible
    load_stage(0); CP_COMMIT();

    for (int s = 0; s < 128; s++) {
        if (s + 1 < 128) load_stage(s + 1);
        CP_COMMIT();
        CP_WAIT1();
        __syncthreads();

        const uint32_t kcoff = (uint32_t)((s & 7) << 7);     // kc*64 bf16 = *128B
        const uint32_t bbuf  = (uint32_t)((s & 1) * BSTG);
        #pragma unroll
        for (int ks = 0; ks < 4; ks++) {
            uint32_t a[4][4], b[4][4];
            #pragma unroll
            for (int mt = 0; mt < 4; mt++)
                ldsm4(a[mt], abase[mt] + kcoff + (uint32_t)(ks * 32));
            #pragma unroll
            for (int p = 0; p < 4; p++)
                ldsm4(b[p], bbase[p] + bbuf + (uint32_t)(ks * 32));
            #pragma unroll
            for (int mt = 0; mt < 4; mt++)
                #pragma unroll
                for (int p = 0; p < 4; p++) {
                    mma16816(c[mt][2 * p],     a[mt], b[p][0], b[p][1]);
                    mma16816(c[mt][2 * p + 1], a[mt], b[p][2], b[p][3]);
                }
        }
        __syncthreads();                        // done reading this buffer

        if ((s & 7) == 7) {
            // ---- epilogue for finished 256-col chunk: exp + masked row sums ----
            const int jc = col0 + ((s >> 3) << 8) + wn * 64 + ((lane & 3) << 1);
            #pragma unroll
            for (int mt = 0; mt < 4; mt++) {
                const int r_lo = r_lo0 + mt * 16, r_hi = r_lo + 8;
                const int lab_lo = r_lo ^ 4096, lab_hi = r_hi ^ 4096;
                float slo = 0.0f, shi = 0.0f;
                #pragma unroll
                for (int nt = 0; nt < 8; nt++) {
                    const int j0 = jc + nt * 8;
                    float d0 = c[mt][nt][0], d1 = c[mt][nt][1];
                    float d2 = c[mt][nt][2], d3 = c[mt][nt][3];
                    float e0 = ex2f(d0 * LOG2E10), e1 = ex2f(d1 * LOG2E10);
                    float e2 = ex2f(d2 * LOG2E10), e3 = ex2f(d3 * LOG2E10);
                    if (j0     != r_lo) slo += e0;
                    if (j0 + 1 != r_lo) slo += e1;
                    if (j0     != r_hi) shi += e2;
                    if (j0 + 1 != r_hi) shi += e3;
                    if (j0     == lab_lo) g_pos[r_lo] = d0;
                    if (j0 + 1 == lab_lo) g_pos[r_lo] = d1;
                    if (j0     == lab_hi) g_pos[r_hi] = d2;
                    if (j0 + 1 == lab_hi) g_pos[r_hi] = d3;
                    c[mt][nt][0] = 0.0f; c[mt][nt][1] = 0.0f;
                    c[mt][nt][2] = 0.0f; c[mt][nt][3] = 0.0f;
                }
                rsum[mt * 2]     += slo;
                rsum[mt * 2 + 1] += shi;
            }
        }
    }

    // ---- deterministic row-sum reduction ----
    // quad reduce: lanes 4q..4q+3 share the same rows (differ only in cols)
    #pragma unroll
    for (int i = 0; i < 8; i++) {
        rsum[i] += __shfl_xor_sync(0xffffffffu, rsum[i], 1);
        rsum[i] += __shfl_xor_sync(0xffffffffu, rsum[i], 2);
    }
    __syncthreads();                            // SMEM free, reuse for reduce
    float* red = (float*)smem;                  // [4 warps_n][128 rows]
    if ((lane & 3) == 0) {
        #pragma unroll
        for (int i = 0; i < 8; i++) {
            int lrow = wm * 64 + (i >> 1) * 16 + (lane >> 2) + (i & 1) * 8;
            red[wn * 128 + lrow] = rsum[i];
        }
    }
    __syncthreads();
    if (tid < 128) {
        float sum = red[tid] + red[128 + tid] + red[256 + tid] + red[384 + tid];
        g_psum[half * NROWS + row0 + tid] = sum;
    }
}

// ============================================================================
// Kernel 3: per-row NLL + per-block reduce (deterministic slots)
// ============================================================================
__global__ void __launch_bounds__(1024) row_reduce_kernel()
{
    const int i = blockIdx.x * 1024 + threadIdx.x;  // 8 x 1024 = 8192
    float s = g_psum[i] + g_psum[NROWS + i];
    float nll = logf(s) - 10.0f * g_pos[i];
    __shared__ float sm[1024];
    sm[threadIdx.x] = nll;
    __syncthreads();
    #pragma unroll
    for (int st = 512; st > 0; st >>= 1) {
        if (threadIdx.x < st) sm[threadIdx.x] += sm[threadIdx.x + st];
        __syncthreads();
    }
    if (threadIdx.x == 0) g_bsum[blockIdx.x] = sm[0];
}

__global__ void finalize_kernel(float* out)
{
    float t = 0.0f;
    #pragma unroll
    for (int i = 0; i < 8; i++) t += g_bsum[i];
    out[0] = t * (1.0f / (float)NROWS);
}

// ============================================================================
// Entry point (graph-capturable: kernel launches only)
// ============================================================================
extern "C" void kernel_launch(void* const* d_in, const int* in_sizes, int n_in,
                              void* d_out, int out_size)
{
    (void)in_sizes; (void)n_in; (void)out_size;
    const float* f1 = (const float*)d_in[0];
    const float* f2 = (const float*)d_in[1];
    float* out = (float*)d_out;

    cudaFuncSetAttribute(infonce_gemm_kernel,
                         cudaFuncAttributeMaxDynamicSharedMemorySize, SMEM_BYTES);

    normalize_kernel<<<NROWS, 128>>>(f1, f2);
    infonce_gemm_kernel<<<128, 256, SMEM_BYTES>>>();
    row_reduce_kernel<<<8, 1024>>>();
    finalize_kernel<<<1, 1>>>(out);
}

// round 7
// speedup vs baseline: 1.6182x; 1.6182x over previous
#include <cuda_runtime.h>
#include <cuda_bf16.h>
#include <cstdint>
#include <cstddef>

// ============================================================================
// Problem constants: B=4096, D=512, 2B=8192 rows, temperature 0.1
// ============================================================================
#define B_ROWS 4096
#define DIM    512
#define NROWS  8192
#define NTILES 64            // 64 row-tiles of 128
#define NPAIRS 2080          // upper triangle incl diagonal
#define GRID_G 152           // GB300 SM count

// Scratch (device globals — no allocation allowed)
__device__ __align__(128) __nv_bfloat16 g_F[NROWS * DIM];  // normalized feats
__device__ float g_acc[NTILES * NTILES * 128];  // [I][J][r] partial exp-sums
__device__ float g_pos[NROWS];                  // positive-pair dot (unscaled)
__device__ float g_bsum[NTILES];                // per-rowtile NLL partials
__device__ int   g_cnt = 0;                     // last-block counter

// ============================================================================
// Arch-neutral PTX helpers (ptxas target is plain sm_103: no 'a' features)
// ============================================================================
static __device__ __forceinline__ uint32_t smem_u32(const void* p) {
    uint32_t a;
    asm("{ .reg .u64 t; cvta.to.shared.u64 t, %1; cvt.u32.u64 %0, t; }" : "=r"(a) : "l"(p));
    return a;
}
static __device__ __forceinline__ void ldsm4(uint32_t* r, uint32_t addr) {
    asm volatile("ldmatrix.sync.aligned.m8n8.x4.shared.b16 {%0,%1,%2,%3}, [%4];"
        : "=r"(r[0]), "=r"(r[1]), "=r"(r[2]), "=r"(r[3]) : "r"(addr));
}
static __device__ __forceinline__ void mma16816(float* c, const uint32_t* a,
                                                uint32_t b0, uint32_t b1) {
    asm volatile(
        "mma.sync.aligned.m16n8k16.row.col.f32.bf16.bf16.f32 "
        "{%0,%1,%2,%3}, {%4,%5,%6,%7}, {%8,%9}, {%0,%1,%2,%3};"
        : "+f"(c[0]), "+f"(c[1]), "+f"(c[2]), "+f"(c[3])
        : "r"(a[0]), "r"(a[1]), "r"(a[2]), "r"(a[3]), "r"(b0), "r"(b1));
}
static __device__ __forceinline__ void cp16(uint32_t dst, const void* src) {
    asm volatile("cp.async.cg.shared.global [%0], [%1], 16;" :: "r"(dst), "l"(src));
}
#define CP_COMMIT() asm volatile("cp.async.commit_group;" ::: "memory")
#define CP_WAIT2()  asm volatile("cp.async.wait_group 2;" ::: "memory")
static __device__ __forceinline__ float ex2f(float x) {
    float y; asm("ex2.approx.ftz.f32 %0, %1;" : "=f"(y) : "f"(x)); return y;
}

// ============================================================================
// SMEM: 4-stage ring; each stage = A(128 rows x 64K bf16, 144B padded rows)
//       + B(same) = 36864 B.  16B row pad => conflict-free ldmatrix.
// ============================================================================
static constexpr int RSTRIDE = 144;             // bytes per 64-K row
static constexpr int STG_B   = 18432;           // B offset within a stage
static constexpr int STG     = 36864;           // stage bytes
static constexpr int SM_REDR = 4 * STG;         // 147456: 2x128 floats
static constexpr int SM_REDC = SM_REDR + 1024;  // 4x128 floats
static constexpr int SMEM_BYTES = SM_REDC + 2048;  // 150528

// ============================================================================
// Kernel 1: fp32 L2-normalize rows of features1|features2 -> g_F (bf16)
// ============================================================================
__global__ void __launch_bounds__(128) normalize_kernel(
    const float* __restrict__ f1, const float* __restrict__ f2)
{
    const int row = blockIdx.x;                 // 0..8191
    const int t = threadIdx.x;                  // 0..127 (4 floats each)
    const float* src = (row < B_ROWS) ? (f1 + (size_t)row * DIM)
                                      : (f2 + (size_t)(row - B_ROWS) * DIM);
    float4 v = ((const float4*)src)[t];
    float ss = v.x * v.x + v.y * v.y + v.z * v.z + v.w * v.w;
    #pragma unroll
    for (int o = 16; o > 0; o >>= 1) ss += __shfl_xor_sync(0xffffffffu, ss, o);
    __shared__ float ws[4];
    if ((t & 31) == 0) ws[t >> 5] = ss;
    __syncthreads();
    ss = ws[0] + ws[1] + ws[2] + ws[3];
    const float scale = 1.0f / fmaxf(sqrtf(ss), 1e-12f);
    __nv_bfloat162* dst = (__nv_bfloat162*)(g_F + (size_t)row * DIM);
    dst[t * 2 + 0] = __floats2bfloat162_rn(v.x * scale, v.y * scale);
    dst[t * 2 + 1] = __floats2bfloat162_rn(v.z * scale, v.w * scale);
}

// ============================================================================
// Kernel 2: symmetric streaming-softmax GEMM over upper-triangle tile pairs.
// 152 persistent CTAs, each a contiguous chunk of the 2080 (I,J) pairs.
// 256 threads = 8 warps, 4(row) x 2(col) grid, warp tile 32x64 of the
// 128x128 tile. 4-stage cp.async ring streams A(I) and B(J) K-slices;
// pipeline is continuous across tile boundaries (single fill bubble).
// ============================================================================
__global__ void __launch_bounds__(256, 1) infonce_sym_kernel()
{
    extern __shared__ __align__(1024) char smem[];
    const uint32_t sb = smem_u32(smem);
    const int tid  = threadIdx.x;
    const int lane = tid & 31;
    const int wid  = tid >> 5;
    const int wm   = wid >> 1;                 // 0..3 : 32-row band
    const int wn   = wid & 1;                  // 0..1 : 64-col band

    // ---- my contiguous chunk of tile pairs: 2080 = 152*13 + 104 ----
    const int cb  = blockIdx.x;
    const int cnt = 13 + (cb < 104 ? 1 : 0);
    int start = cb * 13 + (cb < 104 ? cb : 104);
    int ci = 0;
    { int t = start; while (t >= NTILES - ci) { t -= NTILES - ci; ci++; } start = t; }
    int cj = ci + start;                       // compute cursor (ci,cj)
    int li = ci, lj = cj;                      // loader cursor
    const int NS = cnt * 8;                    // 8 K-stages per tile

    // ---- ldmatrix per-thread base offsets within a stage ----
    const uint32_t aoff = (uint32_t)(
        (wm * 32 + (lane & 7) + ((lane >> 3) & 1) * 8) * RSTRIDE
        + ((lane >> 4) * 8) * 2);
    const uint32_t boff = (uint32_t)(STG_B
        + (wn * 64 + (lane & 7) + (lane >> 4) * 8) * RSTRIDE
        + (((lane >> 3) & 1) * 8) * 2);

    float acc[2][8][4];
    #pragma unroll
    for (int mt = 0; mt < 2; mt++)
        #pragma unroll
        for (int nt = 0; nt < 8; nt++)
            #pragma unroll
            for (int q = 0; q < 4; q++) acc[mt][nt][q] = 0.0f;

    // ---- stage issue: 2048 x 16B cp.async (8/thread): A rows then B rows ----
    auto issue = [&](int gs) {
        const int kc = gs & 7;
        const uint32_t stb = sb + (uint32_t)((gs & 3) * STG);
        const __nv_bfloat16* pa = g_F + ((size_t)li << 7) * DIM + kc * 64;
        const __nv_bfloat16* pb = g_F + ((size_t)lj << 7) * DIM + kc * 64;
        #pragma unroll
        for (int i = 0; i < 4; i++) {
            int idx = tid + (i << 8);          // 0..1023
            int r = idx >> 3, ck = idx & 7;
            cp16(stb + (uint32_t)(r * RSTRIDE + ck * 16),
                 pa + (size_t)r * DIM + ck * 8);
        }
        #pragma unroll
        for (int i = 0; i < 4; i++) {
            int idx = tid + (i << 8);
            int r = idx >> 3, ck = idx & 7;
            cp16(stb + (uint32_t)(STG_B + r * RSTRIDE + ck * 16),
                 pb + (size_t)r * DIM + ck * 8);
        }
        if (kc == 7) { lj++; if (lj == NTILES) { li++; lj = li; } }
    };

    for (int p = 0; p < 3; p++) { issue(p); CP_COMMIT(); }   // cnt>=13 => NS>=8

    float* red_r = (float*)(smem + SM_REDR);
    float* red_c = (float*)(smem + SM_REDC);
    const float LOG2E10 = 14.426950408889634f;  // 10 / ln 2

    for (int gs = 0; gs < NS; gs++) {
        CP_WAIT2();                              // stage gs complete (this thread)
        __syncthreads();                         // visible to all; ring slot free
        if (gs + 3 < NS) issue(gs + 3);
        CP_COMMIT();

        const uint32_t stb = sb + (uint32_t)((gs & 3) * STG);
        #pragma unroll
        for (int ks = 0; ks < 4; ks++) {
            uint32_t a[2][4], b[4][4];
            ldsm4(a[0], stb + aoff + (uint32_t)(ks * 32));
            ldsm4(a[1], stb + aoff + 2304u + (uint32_t)(ks * 32));  // +16 rows
            #pragma unroll
            for (int p = 0; p < 4; p++)
                ldsm4(b[p], stb + boff + (uint32_t)(p * 2304 + ks * 32));
            #pragma unroll
            for (int mt = 0; mt < 2; mt++)
                #pragma unroll
                for (int p = 0; p < 4; p++) {
                    mma16816(acc[mt][2 * p],     a[mt], b[p][0], b[p][1]);
                    mma16816(acc[mt][2 * p + 1], a[mt], b[p][2], b[p][3]);
                }
        }

        if ((gs & 7) == 7) {
            // ======= epilogue for tile (ci,cj): exp + row/col partial sums ====
            const bool isdiag = (ci == cj);
            const bool ispos  = (cj == ci + 32);    // label tile (i^4096)
            float rs[4] = {0.f, 0.f, 0.f, 0.f};     // [mt*2+h] rows
            float cs[16];
            #pragma unroll
            for (int i = 0; i < 16; i++) cs[i] = 0.f;
            #pragma unroll
            for (int mt = 0; mt < 2; mt++)
                #pragma unroll
                for (int nt = 0; nt < 8; nt++)
                    #pragma unroll
                    for (int q = 0; q < 4; q++) {
                        int rl = wm * 32 + mt * 16 + ((q >> 1) << 3) + (lane >> 2);
                        int cl = wn * 64 + nt * 8 + ((lane & 3) << 1) + (q & 1);
                        float d = acc[mt][nt][q];
                        acc[mt][nt][q] = 0.0f;
                        float e = ex2f(d * LOG2E10);
                        bool dg = (rl == cl);
                        if (!(isdiag && dg)) {
                            rs[mt * 2 + (q >> 1)] += e;
                            cs[nt * 2 + (q & 1)]  += e;
                        }
                        if (ispos && dg) {          // sim[i][i^4096]==sim[i^4096][i]
                            g_pos[(ci << 7) + rl] = d;
                            g_pos[(cj << 7) + cl] = d;
                        }
                    }
            // row sums: reduce over lane&3 (same rows, different cols)
            #pragma unroll
            for (int i = 0; i < 4; i++) {
                rs[i] += __shfl_xor_sync(0xffffffffu, rs[i], 1);
                rs[i] += __shfl_xor_sync(0xffffffffu, rs[i], 2);
            }
            // col sums: reduce over lane>>2 (same cols, different rows)
            #pragma unroll
            for (int i = 0; i < 16; i++) {
                cs[i] += __shfl_xor_sync(0xffffffffu, cs[i], 4);
                cs[i] += __shfl_xor_sync(0xffffffffu, cs[i], 8);
                cs[i] += __shfl_xor_sync(0xffffffffu, cs[i], 16);
            }
            if ((lane & 3) == 0) {
                #pragma unroll
                for (int i = 0; i < 4; i++)   // row = wm*32 + mt*16 + h*8 + lane>>2
                    red_r[wn * 128 + wm * 32 + (i >> 1) * 16 + (i & 1) * 8
                          + (lane >> 2)] = rs[i];
            }
            if (lane < 4) {
                #pragma unroll
                for (int i = 0; i < 16; i++)  // col = wn*64 + nt*8 + lane*2 + p
                    red_c[wm * 128 + wn * 64 + (i >> 1) * 8 + lane * 2
                          + (i & 1)] = cs[i];
            }
            __syncthreads();
            if (tid < 128) {
                float rsum = red_r[tid] + red_r[128 + tid];
                g_acc[((ci << 6) + cj) * 128 + tid] = rsum;          // rows of I
                if (!isdiag) {
                    float csum = red_c[tid] + red_c[128 + tid]
                               + red_c[256 + tid] + red_c[384 + tid];
                    g_acc[((cj << 6) + ci) * 128 + tid] = csum;      // rows of J
                }
            }
            cj++; if (cj == NTILES) { ci++; cj = ci; }
            // next loop-top __syncthreads protects red_* reuse
        }
    }
}

// ============================================================================
// Kernel 3: per-row NLL + final mean (last block finishes; deterministic)
// ============================================================================
__global__ void __launch_bounds__(128) reduce_kernel(float* __restrict__ out)
{
    const int b = blockIdx.x, r = threadIdx.x;  // 64 blocks x 128 rows
    const float* base = g_acc + (size_t)b * NTILES * 128;
    float s = 0.0f;
    #pragma unroll 16
    for (int J = 0; J < NTILES; J++) s += base[J * 128 + r];
    float nll = logf(s) - 10.0f * g_pos[b * 128 + r];
    __shared__ float sm[128];
    sm[r] = nll;
    __syncthreads();
    #pragma unroll
    for (int st = 64; st > 0; st >>= 1) {
        if (r < st) sm[r] += sm[r + st];
        __syncthreads();
    }
    if (r == 0) {
        g_bsum[b] = sm[0];
        __threadfence();
        int old = atomicAdd(&g_cnt, 1);
        if (old == NTILES - 1) {                // last block: all partials ready
            volatile float* vb = g_bsum;
            float t = 0.0f;
            for (int i = 0; i < NTILES; i++) t += vb[i];
            out[0] = t * (1.0f / (float)NROWS);
            g_cnt = 0;                          // reset for next graph replay
        }
    }
}

// ============================================================================
// Entry point (graph-capturable: kernel launches only)
// ============================================================================
extern "C" void kernel_launch(void* const* d_in, const int* in_sizes, int n_in,
                              void* d_out, int out_size)
{
    (void)in_sizes; (void)n_in; (void)out_size;
    const float* f1 = (const float*)d_in[0];
    const float* f2 = (const float*)d_in[1];
    float* out = (float*)d_out;

    cudaFuncSetAttribute(infonce_sym_kernel,
                         cudaFuncAttributeMaxDynamicSharedMemorySize, SMEM_BYTES);

    normalize_kernel<<<NROWS, 128>>>(f1, f2);
    infonce_sym_kernel<<<GRID_G, 256, SMEM_BYTES>>>();
    reduce_kernel<<<NTILES, 128>>>(out);
}